// round 9
// baseline (speedup 1.0000x reference)
#include <cuda_runtime.h>
#include <math.h>

#define N_NODES 4096
#define N_GRAPH 8
#define LOG2E   1.4426950408889634f
#define GSTRIDE 4194304   // int4 elements per graph (4096*4096/4)
#define KTOT    (N_NODES * 3)   // 12288
#define GAT_BLOCKS 296          // 2 per SM on 148 SMs
#define FC_CHUNKS 32
#define ROWS_PER_CHUNK (N_NODES / FC_CHUNKS)   // 128
#define KC (ROWS_PER_CHUNK * 3)                // 384

// Persistent scratch (no allocations allowed).
__device__ float4 g_table[N_NODES];           // swizzled: [(j&3)*1024 + (j>>2)] = (d'_j, Wh0, Wh1, Wh2)
__device__ float  g_sprime[N_NODES];          // s_i * log2(e)
__device__ float4 g_meanpart[64];             // per-prep-block sum of Wh (x,y,z used)
__device__ float4 g_part[N_NODES][2][N_GRAPH];// per-row partials: (sum, a0, a1, a2) per graph
__device__ float  g_fcpart[FC_CHUNKS * 100 * N_GRAPH]; // [chunk][o][b]

__device__ __forceinline__ float ex2f_fast(float x) {
    float r; asm("ex2.approx.ftz.f32 %0, %1;" : "=f"(r) : "f"(x)); return r;
}
__device__ __forceinline__ float maskf(int m, float w) {
    return __int_as_float((-m) & __float_as_int(w));
}
__device__ __forceinline__ float elu_fast(float x) {
    return x > 0.f ? x : ex2f_fast(x * LOG2E) - 1.0f;
}

// ---------------------------------------------------------------------------
// Kernel 1: Wh = emb @ W, s,d, swizzled table + per-block Wh sums (for mean).
// 4 lanes per node.
// ---------------------------------------------------------------------------
__global__ void __launch_bounds__(256)
prep_kernel(const float* __restrict__ emb,
            const float* __restrict__ W,
            const float* __restrict__ a) {
    __shared__ float sW[384];
    __shared__ float sa[6];
    __shared__ float red[8][3];
    int tid = threadIdx.x;
    for (int k = tid; k < 384; k += 256) sW[k] = W[k];
    if (tid < 6) sa[tid] = a[tid];
    __syncthreads();

    int t  = blockIdx.x * 256 + tid;      // 0..16383
    int i  = t >> 2;                      // node
    int qd = t & 3;                       // quarter of the feature dim
    const float4* e4 = reinterpret_cast<const float4*>(emb + (size_t)i * 128) + qd * 8;
    float w0 = 0.f, w1 = 0.f, w2 = 0.f;
#pragma unroll
    for (int f4 = 0; f4 < 8; ++f4) {
        float4 e = e4[f4];
        int f = (qd * 8 + f4) * 4;
        w0 = fmaf(e.x, sW[(f+0)*3+0], w0); w1 = fmaf(e.x, sW[(f+0)*3+1], w1); w2 = fmaf(e.x, sW[(f+0)*3+2], w2);
        w0 = fmaf(e.y, sW[(f+1)*3+0], w0); w1 = fmaf(e.y, sW[(f+1)*3+1], w1); w2 = fmaf(e.y, sW[(f+1)*3+2], w2);
        w0 = fmaf(e.z, sW[(f+2)*3+0], w0); w1 = fmaf(e.z, sW[(f+2)*3+1], w1); w2 = fmaf(e.z, sW[(f+2)*3+2], w2);
        w0 = fmaf(e.w, sW[(f+3)*3+0], w0); w1 = fmaf(e.w, sW[(f+3)*3+1], w1); w2 = fmaf(e.w, sW[(f+3)*3+2], w2);
    }
    // after this xor-reduce, every lane of the node group holds the node sums
#pragma unroll
    for (int off = 1; off <= 2; off <<= 1) {
        w0 += __shfl_xor_sync(0xffffffffu, w0, off);
        w1 += __shfl_xor_sync(0xffffffffu, w1, off);
        w2 += __shfl_xor_sync(0xffffffffu, w2, off);
    }
    if (qd == 0) {
        float s = w0*sa[0] + w1*sa[1] + w2*sa[2];
        float d = w0*sa[3] + w1*sa[4] + w2*sa[5];
        g_sprime[i] = s * LOG2E;
        g_table[(i & 3) * 1024 + (i >> 2)] = make_float4(d * LOG2E, w0, w1, w2);
    }
    // block-level Wh sum for the mean fallback (each node counted 4x, fix later)
    float m0 = w0, m1 = w1, m2 = w2;
#pragma unroll
    for (int off = 4; off <= 16; off <<= 1) {
        m0 += __shfl_xor_sync(0xffffffffu, m0, off);
        m1 += __shfl_xor_sync(0xffffffffu, m1, off);
        m2 += __shfl_xor_sync(0xffffffffu, m2, off);
    }
    int lane = tid & 31, wp = tid >> 5;
    if (lane == 0) { red[wp][0] = m0; red[wp][1] = m1; red[wp][2] = m2; }
    __syncthreads();
    if (tid == 0) {
        float t0 = 0.f, t1 = 0.f, t2 = 0.f;
#pragma unroll
        for (int k = 0; k < 8; ++k) { t0 += red[k][0]; t1 += red[k][1]; t2 += red[k][2]; }
        g_meanpart[blockIdx.x] = make_float4(t0 * 0.25f, t1 * 0.25f, t2 * 0.25f, 0.f);
    }
}

// ---------------------------------------------------------------------------
// Kernel 2: fused GAT, exactly balanced (R6 epilogue: always write partials).
// ---------------------------------------------------------------------------
__global__ void __launch_bounds__(256, 2)
gat8_kernel(const int* __restrict__ adj) {
    extern __shared__ float4 tbl[];   // 4096 float4 = 64 KB
    int tid = threadIdx.x;
    for (int idx = tid; idx < N_NODES; idx += 256)
        tbl[idx] = g_table[idx];
    __syncthreads();

    const float4* t0 = tbl;
    const float4* t1 = tbl + 1024;
    const float4* t2 = tbl + 2048;
    const float4* t3 = tbl + 3072;

    int lane = tid & 31;
    int w = blockIdx.x * 8 + (tid >> 5);          // 0..2367
    int qi = (w * 256 + 36) / 37;                 // quarter range [qi, qe)
    int qe = ((w + 1) * 256 + 36) / 37;

    const int4* adj4 = reinterpret_cast<const int4*>(adj);

    while (qi < qe) {
        int r = qi >> 2;
        int rowEnd = min(qe, (r + 1) << 2);
        int q0 = (qi - (r << 2)) << 8;            // start int4-index within row
        int q1 = (rowEnd - (r << 2)) << 8;        // end

        float sp = __ldg(&g_sprime[r]);
        const int4* arow = adj4 + (size_t)r * 1024;

        float sum[N_GRAPH], a0[N_GRAPH], a1[N_GRAPH], a2[N_GRAPH];
#pragma unroll
        for (int b = 0; b < N_GRAPH; ++b) { sum[b] = 0.f; a0[b] = 0.f; a1[b] = 0.f; a2[b] = 0.f; }

        for (int q = q0 + lane; q < q1; q += 32) {
            int4 m[N_GRAPH];
#pragma unroll
            for (int b = 0; b < N_GRAPH; ++b)
                m[b] = __ldcs(arow + (size_t)b * GSTRIDE + q);

            float4 gA = t0[q];
            float4 gB = t1[q];
            float4 gC = t2[q];
            float4 gD = t3[q];

            float xA = sp + gA.x; float wA = ex2f_fast(fmaxf(xA, 0.2f * xA));
            float xB = sp + gB.x; float wB = ex2f_fast(fmaxf(xB, 0.2f * xB));
            float xC = sp + gC.x; float wC = ex2f_fast(fmaxf(xC, 0.2f * xC));
            float xD = sp + gD.x; float wD = ex2f_fast(fmaxf(xD, 0.2f * xD));

#pragma unroll
            for (int b = 0; b < N_GRAPH; ++b) {
                float wx = maskf(m[b].x, wA);
                float wy = maskf(m[b].y, wB);
                float wz = maskf(m[b].z, wC);
                float ww = maskf(m[b].w, wD);
                sum[b] += (wx + wy) + (wz + ww);
                a0[b] = fmaf(wx, gA.y, a0[b]); a0[b] = fmaf(wy, gB.y, a0[b]);
                a0[b] = fmaf(wz, gC.y, a0[b]); a0[b] = fmaf(ww, gD.y, a0[b]);
                a1[b] = fmaf(wx, gA.z, a1[b]); a1[b] = fmaf(wy, gB.z, a1[b]);
                a1[b] = fmaf(wz, gC.z, a1[b]); a1[b] = fmaf(ww, gD.z, a1[b]);
                a2[b] = fmaf(wx, gA.w, a2[b]); a2[b] = fmaf(wy, gB.w, a2[b]);
                a2[b] = fmaf(wz, gC.w, a2[b]); a2[b] = fmaf(ww, gD.w, a2[b]);
            }
        }

#pragma unroll
        for (int b = 0; b < N_GRAPH; ++b) {
#pragma unroll
            for (int off = 16; off; off >>= 1) {
                sum[b] += __shfl_xor_sync(0xffffffffu, sum[b], off);
                a0[b]  += __shfl_xor_sync(0xffffffffu, a0[b],  off);
                a1[b]  += __shfl_xor_sync(0xffffffffu, a1[b],  off);
                a2[b]  += __shfl_xor_sync(0xffffffffu, a2[b],  off);
            }
        }

        if (lane == 0) {
            int slot = (q0 == 0) ? 0 : 1;
            float4* pp = &g_part[r][slot][0];
#pragma unroll
            for (int b = 0; b < N_GRAPH; ++b)
                pp[b] = make_float4(sum[b], a0[b], a1[b], a2[b]);
        }
        qi = rowEnd;
    }
}

// ---------------------------------------------------------------------------
// Kernel 3: per-chunk: combine partials -> h (smem) -> GEMV vs fc1_w slice.
// One block per 128 rows. Absorbs the old combine + mean-finalize + fc_part.
// ---------------------------------------------------------------------------
__global__ void __launch_bounds__(256)
fc_chunk_kernel(const float* __restrict__ fw) {
    __shared__ float hs[N_GRAPH][KC + 4];     // stride 388: conflict-free
    __shared__ float fbk[3];
    int c   = blockIdx.x;                     // 0..31
    int tid = threadIdx.x;
    int lane = tid & 31, warp = tid >> 5;

    // Phase 0: fallback = elu(mean Wh) from the 64 prep partials (warp 0).
    if (warp == 0) {
        float4 v0 = g_meanpart[lane];
        float4 v1 = g_meanpart[lane + 32];
        float m0 = v0.x + v1.x, m1 = v0.y + v1.y, m2 = v0.z + v1.z;
#pragma unroll
        for (int off = 16; off; off >>= 1) {
            m0 += __shfl_xor_sync(0xffffffffu, m0, off);
            m1 += __shfl_xor_sync(0xffffffffu, m1, off);
            m2 += __shfl_xor_sync(0xffffffffu, m2, off);
        }
        if (lane == 0) {
            fbk[0] = elu_fast(m0 * (1.0f / N_NODES));
            fbk[1] = elu_fast(m1 * (1.0f / N_NODES));
            fbk[2] = elu_fast(m2 * (1.0f / N_NODES));
        }
    }
    __syncthreads();

    // Phase 1: combine + normalize + elu into smem. 1024 (row,b) pairs.
#pragma unroll
    for (int s = 0; s < 4; ++s) {
        int idx = s * 256 + tid;              // 0..1023
        int rl = idx >> 3;                    // local row 0..127
        int b  = idx & 7;
        int r  = c * ROWS_PER_CHUNK + rl;
        int w0 = ((r << 2) * 37) >> 8;
        int w3 = (((r << 2) + 3) * 37) >> 8;
        float4 p = g_part[r][0][b];
        if (w0 != w3) {
            float4 p1 = g_part[r][1][b];
            p.x += p1.x; p.y += p1.y; p.z += p1.z; p.w += p1.w;
        }
        float h0, h1, h2;
        if (p.x == 0.0f) {
            h0 = fbk[0]; h1 = fbk[1]; h2 = fbk[2];
        } else {
            float inv = 1.0f / p.x;
            h0 = elu_fast(p.y * inv);
            h1 = elu_fast(p.z * inv);
            h2 = elu_fast(p.w * inv);
        }
        hs[b][rl * 3 + 0] = h0;
        hs[b][rl * 3 + 1] = h1;
        hs[b][rl * 3 + 2] = h2;
    }
    __syncthreads();

    // Phase 2: warp-per-output GEMV over this chunk's 384-k slice.
    for (int o = warp; o < 100; o += 8) {
        const float* wrow = fw + (size_t)o * KTOT + c * KC;
        float acc[N_GRAPH];
#pragma unroll
        for (int b = 0; b < N_GRAPH; ++b) acc[b] = 0.f;
#pragma unroll
        for (int s = 0; s < 12; ++s) {        // 384 / 32
            int k = s * 32 + lane;
            float wv = __ldg(wrow + k);
#pragma unroll
            for (int b = 0; b < N_GRAPH; ++b)
                acc[b] = fmaf(wv, hs[b][k], acc[b]);
        }
#pragma unroll
        for (int b = 0; b < N_GRAPH; ++b)
#pragma unroll
            for (int off = 16; off; off >>= 1)
                acc[b] += __shfl_xor_sync(0xffffffffu, acc[b], off);
        if (lane == 0) {
            float* dst = g_fcpart + ((size_t)c * 100 + o) * N_GRAPH;
#pragma unroll
            for (int b = 0; b < N_GRAPH; ++b) dst[b] = acc[b];
        }
    }
}

// ---------------------------------------------------------------------------
// Kernel 4: final sum over chunks + bias. 800 threads, one per (b,o).
// ---------------------------------------------------------------------------
__global__ void __launch_bounds__(800)
fc_final_kernel(const float* __restrict__ fb, float* __restrict__ out) {
    int t = threadIdx.x;              // 0..799
    int b = t / 100;
    int o = t - b * 100;
    float v = fb[o];
#pragma unroll
    for (int c = 0; c < FC_CHUNKS; ++c)
        v += g_fcpart[((size_t)c * 100 + o) * N_GRAPH + b];
    out[b * 100 + o] = v;
}

// ---------------------------------------------------------------------------
extern "C" void kernel_launch(void* const* d_in, const int* in_sizes, int n_in,
                              void* d_out, int out_size) {
    const int*   adj = (const int*)d_in[0];
    const float* emb = (const float*)d_in[1];
    const float* W   = (const float*)d_in[2];
    const float* a   = (const float*)d_in[3];
    const float* fw  = (const float*)d_in[4];
    const float* fb  = (const float*)d_in[5];
    float* out = (float*)d_out;

    cudaFuncSetAttribute(gat8_kernel, cudaFuncAttributeMaxDynamicSharedMemorySize, 65536);

    prep_kernel<<<64, 256>>>(emb, W, a);
    gat8_kernel<<<GAT_BLOCKS, 256, 65536>>>(adj);
    fc_chunk_kernel<<<FC_CHUNKS, 256>>>(fw);
    fc_final_kernel<<<1, 800>>>(fb, out);
}